// round 2
// baseline (speedup 1.0000x reference)
#include <cuda_runtime.h>
#include <cuda_bf16.h>

// y[b, f*C + c] = sum_hw x[b,c,hw] * kern[f,c,hw]
// B=256, F=16, C=256, HW=1024
// Grid: (C=256, B/BT=2). Block: 256 threads (8 warps).
// Each block: one c, 128-row b-tile, full F=16, K=1024 in chunks of 64,
// software-pipelined (register prefetch of next chunk during compute).
// Thread tile: 2b x 4f accumulators.

#define B_DIM 256
#define F_DIM 16
#define C_DIM 256
#define HW_DIM 1024

#define BT 128     // b-tile per block
#define KC 64      // k-chunk staged in shared
#define THREADS 256

__global__ __launch_bounds__(THREADS, 4)
void spatial_emb_kernel(const float* __restrict__ x,
                        const float* __restrict__ kern,
                        float* __restrict__ out) {
    const int c  = blockIdx.x;        // 0..255
    const int bt = blockIdx.y;        // 0..1
    const int t  = threadIdx.x;       // 0..255
    const int tb = t & 63;            // b-pair index -> rows tb*2, tb*2+1
    const int tf = t >> 6;            // f-group -> f = tf*4 .. tf*4+3

    // Transposed shared tiles: [k][m] so fragment reads are vector LDS.
    __shared__ float xs[KC][BT];      // 32 KB
    __shared__ float ks[KC][F_DIM];   // 4 KB

    // Global load roles:
    //  - x: thread t loads row (t&127), cols [half*32, half*32+32) of the chunk,
    //       half = t>>7. 8 x float4 per thread per chunk.
    //  - kern: thread t loads f = t>>4, 4 floats at col (t&15)*4.
    const int xr   = t & 127;
    const int half = t >> 7;               // 0 or 1
    const int xcol = half * 32;            // col offset within chunk
    const int b_row = bt * BT + xr;
    const float* xrow = x + ((size_t)b_row * C_DIM + c) * HW_DIM;

    const int lf = t >> 4;                 // 0..15
    const int lh = (t & 15) * 4;           // 0,4,...,60
    const float* krow = kern + ((size_t)lf * C_DIM + c) * HW_DIM;

    float acc[2][4];
    #pragma unroll
    for (int i = 0; i < 2; i++)
        #pragma unroll
        for (int j = 0; j < 4; j++)
            acc[i][j] = 0.0f;

    float4 xv[8];
    float4 kv;

    // Prefetch chunk 0
    #pragma unroll
    for (int q = 0; q < 8; q++)
        xv[q] = *(const float4*)(xrow + xcol + q * 4);
    kv = *(const float4*)(krow + lh);

    for (int k0 = 0; k0 < HW_DIM; k0 += KC) {
        __syncthreads();   // previous compute done -> smem safe to overwrite

        // Commit staged registers to shared (transposed)
        #pragma unroll
        for (int q = 0; q < 8; q++) {
            xs[xcol + q * 4 + 0][xr] = xv[q].x;
            xs[xcol + q * 4 + 1][xr] = xv[q].y;
            xs[xcol + q * 4 + 2][xr] = xv[q].z;
            xs[xcol + q * 4 + 3][xr] = xv[q].w;
        }
        ks[lh + 0][lf] = kv.x;
        ks[lh + 1][lf] = kv.y;
        ks[lh + 2][lf] = kv.z;
        ks[lh + 3][lf] = kv.w;

        __syncthreads();

        // Prefetch NEXT chunk while computing this one (latency hidden by 64 k-iters)
        if (k0 + KC < HW_DIM) {
            const float* xnext = xrow + (k0 + KC) + xcol;
            #pragma unroll
            for (int q = 0; q < 8; q++)
                xv[q] = *(const float4*)(xnext + q * 4);
            kv = *(const float4*)(krow + (k0 + KC) + lh);
        }

        // Compute: 64 k-iters, 8 FFMA each
        #pragma unroll 16
        for (int k = 0; k < KC; k++) {
            float2 a = *(const float2*)&xs[k][tb * 2];
            float4 b = *(const float4*)&ks[k][tf * 4];
            acc[0][0] += a.x * b.x;  acc[0][1] += a.x * b.y;
            acc[0][2] += a.x * b.z;  acc[0][3] += a.x * b.w;
            acc[1][0] += a.y * b.x;  acc[1][1] += a.y * b.y;
            acc[1][2] += a.y * b.z;  acc[1][3] += a.y * b.w;
        }
    }

    // out[b, f*C + c], b = bt*BT + tb*2 + i, f = tf*4 + j
    #pragma unroll
    for (int i = 0; i < 2; i++) {
        const int b = bt * BT + tb * 2 + i;
        float* orow = out + (size_t)b * (F_DIM * C_DIM) + c;
        #pragma unroll
        for (int j = 0; j < 4; j++) {
            const int f = tf * 4 + j;
            orow[(size_t)f * C_DIM] = acc[i][j];
        }
    }
}

extern "C" void kernel_launch(void* const* d_in, const int* in_sizes, int n_in,
                              void* d_out, int out_size) {
    const float* x    = (const float*)d_in[0];
    const float* kern = (const float*)d_in[1];
    float* out        = (float*)d_out;

    dim3 grid(C_DIM, B_DIM / BT);   // (256, 2)
    spatial_emb_kernel<<<grid, THREADS>>>(x, kern, out);
}

// round 4
// speedup vs baseline: 1.4228x; 1.4228x over previous
#include <cuda_runtime.h>
#include <cuda_bf16.h>

// y[b, f*C + c] = sum_hw x[b,c,hw] * kern[f,c,hw]
// B=256, F=16, C=256, HW=1024
// Grid: (C=256, 2). Block: 128 threads. Thread = one b; 16 f-accumulators in
// registers as 8 packed f32x2. x staged coalesced through smem; k broadcast
// from smem as ulonglong2 pairs; fma.rn.f32x2 compute.

#define B_DIM 256
#define F_DIM 16
#define C_DIM 256
#define HW_DIM 1024

#define KC 32        // k-chunk
#define THREADS 128
#define XS_PITCH 36  // pad for conflict-free LDS.128 / STS.128

__device__ __forceinline__ unsigned long long fma2(unsigned long long a,
                                                   unsigned long long b,
                                                   unsigned long long c) {
    unsigned long long d;
    asm("fma.rn.f32x2 %0, %1, %2, %3;" : "=l"(d) : "l"(a), "l"(b), "l"(c));
    return d;
}

__device__ __forceinline__ unsigned long long dup2(float v) {
    unsigned long long d;
    asm("mov.b64 %0, {%1, %1};" : "=l"(d) : "f"(v));
    return d;
}

__global__ __launch_bounds__(THREADS, 6)
void spatial_emb_kernel(const float* __restrict__ x,
                        const float* __restrict__ kern,
                        float* __restrict__ out) {
    const int c  = blockIdx.x;          // 0..255
    const int bh = blockIdx.y;          // 0..1 (b half)
    const int t  = threadIdx.x;         // 0..127
    const int w  = t >> 5;              // warp 0..3
    const int l  = t & 31;              // lane

    __shared__ float xs[128][XS_PITCH]; // 18 KB, row = local b, col = k
    __shared__ float ks[KC][F_DIM];     // 2 KB,  row = k, col = f (pairs contiguous)

    // ---- x staging role: warp w covers local rows [w*32, w*32+32).
    // Per iteration it (0..7): lane l -> row w*32 + it*4 + (l>>3), col (l&7)*4.
    const int xrow0 = w * 32 + (l >> 3);   // +4 per iteration
    const int xcol  = (l & 7) * 4;
    const float* xg = x + ((size_t)(bh * 128 + xrow0) * C_DIM + c) * HW_DIM + xcol;
    const size_t xrow_stride4 = (size_t)4 * C_DIM * HW_DIM;  // 4 rows

    // ---- k staging role: thread t -> f = t>>3, cols (t&7)*4 .. +3
    const int kf = t >> 3;              // 0..15
    const int kk = (t & 7) * 4;         // 0..28
    const float* kg = kern + ((size_t)kf * C_DIM + c) * HW_DIM + kk;

    unsigned long long acc[8];
    #pragma unroll
    for (int j = 0; j < 8; j++) acc[j] = 0ull;

    float4 xv[8];
    float4 kv;

    // Prefetch chunk 0
    #pragma unroll
    for (int it = 0; it < 8; it++)
        xv[it] = *(const float4*)(xg + it * xrow_stride4);
    kv = *(const float4*)(kg);

    for (int k0 = 0; k0 < HW_DIM; k0 += KC) {
        __syncthreads();   // previous compute done

        // Commit staged regs to smem
        #pragma unroll
        for (int it = 0; it < 8; it++)
            *(float4*)&xs[xrow0 + it * 4][xcol] = xv[it];
        ks[kk + 0][kf] = kv.x;
        ks[kk + 1][kf] = kv.y;
        ks[kk + 2][kf] = kv.z;
        ks[kk + 3][kf] = kv.w;

        __syncthreads();

        // Prefetch next chunk during compute
        if (k0 + KC < HW_DIM) {
            const float* xn = xg + (k0 + KC);
            #pragma unroll
            for (int it = 0; it < 8; it++)
                xv[it] = *(const float4*)(xn + it * xrow_stride4);
            kv = *(const float4*)(kg + k0 + KC);
        }

        // Compute: thread t = local b row t.
        #pragma unroll
        for (int k4 = 0; k4 < KC / 4; k4++) {
            float4 xf = *(const float4*)&xs[t][k4 * 4];
            #pragma unroll
            for (int j = 0; j < 4; j++) {
                const int k = k4 * 4 + j;
                float xvv = (j == 0) ? xf.x : (j == 1) ? xf.y : (j == 2) ? xf.z : xf.w;
                unsigned long long xx = dup2(xvv);
                ulonglong2 p0 = *(const ulonglong2*)&ks[k][0];
                ulonglong2 p1 = *(const ulonglong2*)&ks[k][4];
                ulonglong2 p2 = *(const ulonglong2*)&ks[k][8];
                ulonglong2 p3 = *(const ulonglong2*)&ks[k][12];
                acc[0] = fma2(xx, p0.x, acc[0]);
                acc[1] = fma2(xx, p0.y, acc[1]);
                acc[2] = fma2(xx, p1.x, acc[2]);
                acc[3] = fma2(xx, p1.y, acc[3]);
                acc[4] = fma2(xx, p2.x, acc[4]);
                acc[5] = fma2(xx, p2.y, acc[5]);
                acc[6] = fma2(xx, p3.x, acc[6]);
                acc[7] = fma2(xx, p3.y, acc[7]);
            }
        }
    }

    // Output: b = bh*128 + t; out[b, f*C + c], acc[j] = (f=2j, f=2j+1)
    const int b = bh * 128 + t;
    float* orow = out + (size_t)b * (F_DIM * C_DIM) + c;
    #pragma unroll
    for (int j = 0; j < 8; j++) {
        unsigned int lo, hi;
        asm("mov.b64 {%0, %1}, %2;" : "=r"(lo), "=r"(hi) : "l"(acc[j]));
        orow[(size_t)(2 * j + 0) * C_DIM] = __uint_as_float(lo);
        orow[(size_t)(2 * j + 1) * C_DIM] = __uint_as_float(hi);
    }
}

extern "C" void kernel_launch(void* const* d_in, const int* in_sizes, int n_in,
                              void* d_out, int out_size) {
    const float* x    = (const float*)d_in[0];
    const float* kern = (const float*)d_in[1];
    float* out        = (float*)d_out;

    dim3 grid(C_DIM, 2);
    spatial_emb_kernel<<<grid, THREADS>>>(x, kern, out);
}

// round 6
// speedup vs baseline: 1.6465x; 1.1572x over previous
#include <cuda_runtime.h>
#include <cuda_bf16.h>
#include <cstdint>

// y[b, f*C + c] = sum_hw x[b,c,hw] * kern[f,c,hw]
// B=256, F=16, C=256, HW=1024
// Grid: (C=256, B/128=2, KSPLIT=4). Block: 128 threads, thread = one b row.
// Split-K partials combined via atomicAdd after a zero-init kernel (same graph).
// x staged global->smem via cp.async (double-buffered); k fragment staged
// transposed via registers. Compute: packed fma.rn.f32x2, 16 f-accumulators.

#define B_DIM 256
#define F_DIM 16
#define C_DIM 256
#define HW_DIM 1024

#define KC 16
#define THREADS 128
#define XS_PITCH 20                   // floats; 80B row, 16B aligned
#define KSPLIT 4
#define KSLICE (HW_DIM / KSPLIT)      // 256
#define NCHUNK (KSLICE / KC)          // 16

__device__ __forceinline__ unsigned long long fma2(unsigned long long a,
                                                   unsigned long long b,
                                                   unsigned long long c) {
    unsigned long long d;
    asm("fma.rn.f32x2 %0, %1, %2, %3;" : "=l"(d) : "l"(a), "l"(b), "l"(c));
    return d;
}

__device__ __forceinline__ unsigned long long dup2(float v) {
    unsigned long long d;
    asm("mov.b64 %0, {%1, %1};" : "=l"(d) : "f"(v));
    return d;
}

// Grid-stride zero-init of the output (runs inside the captured graph each replay).
__global__ void zero_kernel(float* __restrict__ out, int n) {
    for (int i = blockIdx.x * blockDim.x + threadIdx.x; i < n;
         i += gridDim.x * blockDim.x)
        out[i] = 0.0f;
}

__global__ __launch_bounds__(THREADS, 8)
void spatial_emb_kernel(const float* __restrict__ x,
                        const float* __restrict__ kern,
                        float* __restrict__ out) {
    const int c  = blockIdx.x;          // channel
    const int bh = blockIdx.y;          // b half
    const int kh = blockIdx.z;          // k slice
    const int t  = threadIdx.x;

    __shared__ float xs[2][128][XS_PITCH];  // [buf][local b][k]
    __shared__ float ks[2][KC][F_DIM];      // [buf][k][f]

    // x staging: thread covers rows xr, xr+32, xr+64, xr+96 at cols xc..xc+3.
    // A warp's 32 lanes cover 8 consecutive b-rows x 16 floats: fully-used
    // 128B sectors, 4 lines per LDGSTS wave.
    const int xr = t >> 2;              // 0..31
    const int xc = (t & 3) * 4;         // 0,4,8,12
    const float* xg = x + ((size_t)(bh * 128 + xr) * C_DIM + c) * HW_DIM
                        + (size_t)kh * KSLICE + xc;
    const size_t xrs = (size_t)32 * C_DIM * HW_DIM;   // 32 b-rows

    // k staging: thread -> f = t>>3, k-cols kk, kk+1 (transposed store)
    const int kf = t >> 3;              // 0..15
    const int kk = (t & 7) * 2;         // 0..14
    const float* kg = kern + ((size_t)kf * C_DIM + c) * HW_DIM
                           + (size_t)kh * KSLICE + kk;

    unsigned long long acc[8];
    #pragma unroll
    for (int j = 0; j < 8; j++) acc[j] = 0ull;

    // ---- prologue: chunk 0 cp.async in flight; chunk 1 k-frag in regs
    {
        #pragma unroll
        for (int it = 0; it < 4; it++) {
            uint32_t dst = (uint32_t)__cvta_generic_to_shared(&xs[0][xr + it * 32][xc]);
            const float* src = xg + it * xrs;
            asm volatile("cp.async.cg.shared.global [%0], [%1], 16;\n"
                         :: "r"(dst), "l"(src));
        }
        asm volatile("cp.async.commit_group;\n");
    }
    float2 kv = *(const float2*)kg;           // chunk 0 frag
    ks[0][kk + 0][kf] = kv.x;
    ks[0][kk + 1][kf] = kv.y;
    kv = *(const float2*)(kg + KC);           // chunk 1 frag

    int buf = 0;
    for (int ch = 0; ch < NCHUNK; ch++) {
        asm volatile("cp.async.wait_group 0;\n" ::: "memory");
        __syncthreads();   // chunk ch data visible; all threads done with ch-1

        if (ch + 1 < NCHUNK) {
            // issue chunk ch+1 into the other buffer (flies during compute)
            #pragma unroll
            for (int it = 0; it < 4; it++) {
                uint32_t dst = (uint32_t)__cvta_generic_to_shared(&xs[buf ^ 1][xr + it * 32][xc]);
                const float* src = xg + (size_t)(ch + 1) * KC + it * xrs;
                asm volatile("cp.async.cg.shared.global [%0], [%1], 16;\n"
                             :: "r"(dst), "l"(src));
            }
            asm volatile("cp.async.commit_group;\n");
            ks[buf ^ 1][kk + 0][kf] = kv.x;
            ks[buf ^ 1][kk + 1][kf] = kv.y;
            if (ch + 2 < NCHUNK)
                kv = *(const float2*)(kg + (size_t)(ch + 2) * KC);
        }

        // ---- compute chunk ch: thread t = local b row t
        #pragma unroll
        for (int k4 = 0; k4 < KC / 4; k4++) {
            float4 xf = *(const float4*)&xs[buf][t][k4 * 4];
            #pragma unroll
            for (int j = 0; j < 4; j++) {
                const int k = k4 * 4 + j;
                float xvv = (j == 0) ? xf.x : (j == 1) ? xf.y : (j == 2) ? xf.z : xf.w;
                unsigned long long xx = dup2(xvv);
                ulonglong2 p0 = *(const ulonglong2*)&ks[buf][k][0];
                ulonglong2 p1 = *(const ulonglong2*)&ks[buf][k][4];
                ulonglong2 p2 = *(const ulonglong2*)&ks[buf][k][8];
                ulonglong2 p3 = *(const ulonglong2*)&ks[buf][k][12];
                acc[0] = fma2(xx, p0.x, acc[0]);
                acc[1] = fma2(xx, p0.y, acc[1]);
                acc[2] = fma2(xx, p1.x, acc[2]);
                acc[3] = fma2(xx, p1.y, acc[3]);
                acc[4] = fma2(xx, p2.x, acc[4]);
                acc[5] = fma2(xx, p2.y, acc[5]);
                acc[6] = fma2(xx, p3.x, acc[6]);
                acc[7] = fma2(xx, p3.y, acc[7]);
            }
        }
        buf ^= 1;
    }

    // ---- output: b = bh*128 + t; split-K partials combined with atomicAdd (REDG)
    const int b = bh * 128 + t;
    float* orow = out + (size_t)b * (F_DIM * C_DIM) + c;
    #pragma unroll
    for (int j = 0; j < 8; j++) {
        unsigned int lo, hi;
        asm("mov.b64 {%0, %1}, %2;" : "=r"(lo), "=r"(hi) : "l"(acc[j]));
        atomicAdd(&orow[(size_t)(2 * j + 0) * C_DIM], __uint_as_float(lo));
        atomicAdd(&orow[(size_t)(2 * j + 1) * C_DIM], __uint_as_float(hi));
    }
}

extern "C" void kernel_launch(void* const* d_in, const int* in_sizes, int n_in,
                              void* d_out, int out_size) {
    const float* x    = (const float*)d_in[0];
    const float* kern = (const float*)d_in[1];
    float* out        = (float*)d_out;

    zero_kernel<<<512, 256>>>(out, out_size);

    dim3 grid(C_DIM, B_DIM / 128, KSPLIT);   // (256, 2, 4)
    spatial_emb_kernel<<<grid, THREADS>>>(x, kern, out);
}

// round 7
// speedup vs baseline: 2.0040x; 1.2171x over previous
#include <cuda_runtime.h>
#include <cuda_bf16.h>
#include <cstdint>

// y[b, f*C + c] = sum_hw x[b,c,hw] * kern[f,c,hw]
// B=256, F=16, C=256, HW=1024
// Grid: (C=256, KSPLIT=4). Block: 128 threads; thread = TWO b rows (t, t+128),
// so each ks broadcast feeds 16 FMA2 (halves L1 wavefronts per FLOP).
// Split-K partials combined via atomicAdd after a zero-init kernel.
// x staged global->smem via cp.async, double-buffered; fma.rn.f32x2 compute.

#define B_DIM 256
#define F_DIM 16
#define C_DIM 256
#define HW_DIM 1024

#define KC 16
#define THREADS 128
#define XS_PITCH 20                   // floats; conflict-free LDS.128 pattern
#define KSPLIT 4
#define KSLICE (HW_DIM / KSPLIT)      // 256
#define NCHUNK (KSLICE / KC)          // 16

__device__ __forceinline__ unsigned long long fma2(unsigned long long a,
                                                   unsigned long long b,
                                                   unsigned long long c) {
    unsigned long long d;
    asm("fma.rn.f32x2 %0, %1, %2, %3;" : "=l"(d) : "l"(a), "l"(b), "l"(c));
    return d;
}

__device__ __forceinline__ unsigned long long dup2(float v) {
    unsigned long long d;
    asm("mov.b64 %0, {%1, %1};" : "=l"(d) : "f"(v));
    return d;
}

__global__ void zero_kernel(float* __restrict__ out, int n) {
    for (int i = blockIdx.x * blockDim.x + threadIdx.x; i < n;
         i += gridDim.x * blockDim.x)
        out[i] = 0.0f;
}

__global__ __launch_bounds__(THREADS, 5)
void spatial_emb_kernel(const float* __restrict__ x,
                        const float* __restrict__ kern,
                        float* __restrict__ out) {
    const int c  = blockIdx.x;          // channel
    const int kh = blockIdx.y;          // k slice
    const int t  = threadIdx.x;

    __shared__ float xs[2][B_DIM][XS_PITCH];  // [buf][b][k]  40 KB
    __shared__ float ks[2][KC][F_DIM];        // [buf][k][f]   2 KB

    // x staging: 8 iterations; it covers rows xr + it*32 at cols xc..xc+3.
    const int xr = t >> 2;              // 0..31
    const int xc = (t & 3) * 4;         // 0,4,8,12
    const float* xg = x + ((size_t)xr * C_DIM + c) * HW_DIM
                        + (size_t)kh * KSLICE + xc;
    const size_t xrs = (size_t)32 * C_DIM * HW_DIM;   // 32 b-rows

    // k staging: thread -> f = t>>3, k-cols kk, kk+1 (transposed store)
    const int kf = t >> 3;              // 0..15
    const int kk = (t & 7) * 2;         // 0..14
    const float* kg = kern + ((size_t)kf * C_DIM + c) * HW_DIM
                           + (size_t)kh * KSLICE + kk;

    unsigned long long accA[8], accB[8];   // rows t and t+128, 16 f each
    #pragma unroll
    for (int j = 0; j < 8; j++) { accA[j] = 0ull; accB[j] = 0ull; }

    // ---- prologue: chunk 0 cp.async in flight; chunk 1 k-frag in regs
    {
        #pragma unroll
        for (int it = 0; it < 8; it++) {
            uint32_t dst = (uint32_t)__cvta_generic_to_shared(&xs[0][xr + it * 32][xc]);
            const float* src = xg + it * xrs;
            asm volatile("cp.async.cg.shared.global [%0], [%1], 16;\n"
                         :: "r"(dst), "l"(src));
        }
        asm volatile("cp.async.commit_group;\n");
    }
    float2 kv = *(const float2*)kg;           // chunk 0 frag
    ks[0][kk + 0][kf] = kv.x;
    ks[0][kk + 1][kf] = kv.y;
    kv = *(const float2*)(kg + KC);           // chunk 1 frag

    int buf = 0;
    for (int ch = 0; ch < NCHUNK; ch++) {
        asm volatile("cp.async.wait_group 0;\n" ::: "memory");
        __syncthreads();   // chunk ch visible; all threads done with ch-1

        if (ch + 1 < NCHUNK) {
            #pragma unroll
            for (int it = 0; it < 8; it++) {
                uint32_t dst = (uint32_t)__cvta_generic_to_shared(&xs[buf ^ 1][xr + it * 32][xc]);
                const float* src = xg + (size_t)(ch + 1) * KC + it * xrs;
                asm volatile("cp.async.cg.shared.global [%0], [%1], 16;\n"
                             :: "r"(dst), "l"(src));
            }
            asm volatile("cp.async.commit_group;\n");
            ks[buf ^ 1][kk + 0][kf] = kv.x;
            ks[buf ^ 1][kk + 1][kf] = kv.y;
            if (ch + 2 < NCHUNK)
                kv = *(const float2*)(kg + (size_t)(ch + 2) * KC);
        }

        // ---- compute chunk ch: thread t handles b rows t and t+128
        #pragma unroll
        for (int k4 = 0; k4 < KC / 4; k4++) {
            float4 xfa = *(const float4*)&xs[buf][t      ][k4 * 4];
            float4 xfb = *(const float4*)&xs[buf][t + 128][k4 * 4];
            #pragma unroll
            for (int j = 0; j < 4; j++) {
                const int k = k4 * 4 + j;
                float va = (j == 0) ? xfa.x : (j == 1) ? xfa.y : (j == 2) ? xfa.z : xfa.w;
                float vb = (j == 0) ? xfb.x : (j == 1) ? xfb.y : (j == 2) ? xfb.z : xfb.w;
                unsigned long long xa = dup2(va);
                unsigned long long xb = dup2(vb);
                ulonglong2 p0 = *(const ulonglong2*)&ks[buf][k][0];
                ulonglong2 p1 = *(const ulonglong2*)&ks[buf][k][4];
                ulonglong2 p2 = *(const ulonglong2*)&ks[buf][k][8];
                ulonglong2 p3 = *(const ulonglong2*)&ks[buf][k][12];
                accA[0] = fma2(xa, p0.x, accA[0]);  accB[0] = fma2(xb, p0.x, accB[0]);
                accA[1] = fma2(xa, p0.y, accA[1]);  accB[1] = fma2(xb, p0.y, accB[1]);
                accA[2] = fma2(xa, p1.x, accA[2]);  accB[2] = fma2(xb, p1.x, accB[2]);
                accA[3] = fma2(xa, p1.y, accA[3]);  accB[3] = fma2(xb, p1.y, accB[3]);
                accA[4] = fma2(xa, p2.x, accA[4]);  accB[4] = fma2(xb, p2.x, accB[4]);
                accA[5] = fma2(xa, p2.y, accA[5]);  accB[5] = fma2(xb, p2.y, accB[5]);
                accA[6] = fma2(xa, p3.x, accA[6]);  accB[6] = fma2(xb, p3.x, accB[6]);
                accA[7] = fma2(xa, p3.y, accA[7]);  accB[7] = fma2(xb, p3.y, accB[7]);
            }
        }
        buf ^= 1;
    }

    // ---- output: split-K partials combined with atomicAdd (REDG)
    float* orowA = out + (size_t)t * (F_DIM * C_DIM) + c;
    float* orowB = out + (size_t)(t + 128) * (F_DIM * C_DIM) + c;
    #pragma unroll
    for (int j = 0; j < 8; j++) {
        unsigned int lo, hi;
        asm("mov.b64 {%0, %1}, %2;" : "=r"(lo), "=r"(hi) : "l"(accA[j]));
        atomicAdd(&orowA[(size_t)(2 * j + 0) * C_DIM], __uint_as_float(lo));
        atomicAdd(&orowA[(size_t)(2 * j + 1) * C_DIM], __uint_as_float(hi));
        asm("mov.b64 {%0, %1}, %2;" : "=r"(lo), "=r"(hi) : "l"(accB[j]));
        atomicAdd(&orowB[(size_t)(2 * j + 0) * C_DIM], __uint_as_float(lo));
        atomicAdd(&orowB[(size_t)(2 * j + 1) * C_DIM], __uint_as_float(hi));
    }
}

extern "C" void kernel_launch(void* const* d_in, const int* in_sizes, int n_in,
                              void* d_out, int out_size) {
    const float* x    = (const float*)d_in[0];
    const float* kern = (const float*)d_in[1];
    float* out        = (float*)d_out;

    zero_kernel<<<512, 256>>>(out, out_size);

    dim3 grid(C_DIM, KSPLIT);   // (256, 4)
    spatial_emb_kernel<<<grid, THREADS>>>(x, kern, out);
}